// round 11
// baseline (speedup 1.0000x reference)
#include <cuda_runtime.h>
#include <cuda_bf16.h>
#include <mma.h>
#include <cstdint>

using namespace nvcuda;

#define D       256
#define NB      30
#define EPG     240
#define NGRAPH  2048
#define NE      (NGRAPH * EPG)
#define NCTA    (NGRAPH / 2)
#define LDH     264

// ---------------- device scratch ----------------
static __device__ float d_Wg2[5 * D];
static __device__ float d_biasA[D];
static __device__ float d_tab2[11 * D];
static __device__ float d_gcat[NGRAPH * 4 * D];
static __device__ __align__(16) __nv_bfloat16 d_Wb[3 * 2 * 256 * 512];     // [L][p][k][n']
static __device__ __align__(16) __nv_bfloat16 d_Wagg_b[2 * 1024 * 256];    // [p][k][n]
static __device__ __align__(16) __nv_bfloat16 d_Wmv_b[2 * 256 * 512];      // [p][k][mu|var]

// ---------------- helpers ----------------
__device__ __forceinline__ uint32_t smem_u32(const void* p) {
    uint32_t a;
    asm("{ .reg .u64 t; cvta.to.shared.u64 t, %1; cvt.u32.u64 %0, t; }" : "=r"(a) : "l"(p));
    return a;
}
__device__ __forceinline__ void cpa16(uint32_t dst, const void* src) {
    asm volatile("cp.async.cg.shared.global [%0], [%1], 16;" :: "r"(dst), "l"(src));
}
#define CPA_COMMIT() asm volatile("cp.async.commit_group;" ::: "memory")
#define CPA_WAIT(n)  asm volatile("cp.async.wait_group %0;" :: "n"(n) : "memory")

// ---------------- precompute: fold encoder ----------------
__global__ void precompute_kernel(const float* __restrict__ Wgeo, const float* __restrict__ bgeo,
                                  const float* __restrict__ emb, const float* __restrict__ Wlot,
                                  const float* __restrict__ blot) {
    const int r = blockIdx.x, t = threadIdx.x;
    float acc = 0.f;
    if (r < 5) {
        #pragma unroll 8
        for (int k = 0; k < D; k++) acc = fmaf(Wgeo[r * D + k], Wlot[k * D + t], acc);
        d_Wg2[r * D + t] = acc;
    } else if (r == 5) {
        #pragma unroll 8
        for (int k = 0; k < D; k++) acc = fmaf(bgeo[k], Wlot[k * D + t], acc);
        d_biasA[t] = acc + blot[t];
    } else {
        const int s = r - 6;
        #pragma unroll 8
        for (int k = 0; k < D; k++) acc = fmaf(emb[s * D + k], Wlot[(D + k) * D + t], acc);
        d_tab2[s * D + t] = acc;
    }
}

// ---- layer weights: bf16 hi/lo, [k][n'] with the warp-permutation on n' ----
__global__ void wsplit_kernel(const float* __restrict__ W1, const float* __restrict__ W2,
                              const float* __restrict__ W3) {
    const int L = blockIdx.x >> 9, r = blockIdx.x & 511;   // r = tb*256 + k
    const int tb = r >> 8, k = r & 255, c = threadIdx.x;
    const float* W = (L == 0) ? W1 : (L == 1) ? W2 : W3;
    const float w = W[r * 256 + c];
    const __nv_bfloat16 hi = __float2bfloat16(w);
    const __nv_bfloat16 lo = __float2bfloat16(w - __bfloat162float(hi));
    const int np = ((c >> 5) * 64) + tb * 32 + (c & 31);
    d_Wb[((size_t)(L * 2 + 0) * 256 + k) * 512 + np] = hi;
    d_Wb[((size_t)(L * 2 + 1) * 256 + k) * 512 + np] = lo;
}

// ---- head weights: bf16 hi/lo splits ----
__global__ void whead_agg(const float* __restrict__ Wagg) {   // grid 1024 x 256
    const int k = blockIdx.x, n = threadIdx.x;
    const float w = Wagg[k * 256 + n];
    const __nv_bfloat16 hi = __float2bfloat16(w);
    d_Wagg_b[(size_t)(0 * 1024 + k) * 256 + n] = hi;
    d_Wagg_b[(size_t)(1 * 1024 + k) * 256 + n] = __float2bfloat16(w - __bfloat162float(hi));
}
__global__ void whead_mv(const float* __restrict__ Wmu, const float* __restrict__ Wvar) {  // 256 x 512
    const int k = blockIdx.x, n = threadIdx.x;
    const float w = (n < 256) ? Wmu[k * 256 + n] : Wvar[k * 256 + (n - 256)];
    const __nv_bfloat16 hi = __float2bfloat16(w);
    d_Wmv_b[(size_t)(0 * 256 + k) * 512 + n] = hi;
    d_Wmv_b[(size_t)(1 * 256 + k) * 512 + n] = __float2bfloat16(w - __bfloat162float(hi));
}

// ---------------- SMEM layout gnn_main (bytes) ----------------
#define SB_HHI   0         // 64x264 bf16
#define SB_HLO   33792
#define SB_BST   67584     // 2 bufs x 2 p x 16x520 bf16 = 66560
#define SB_SCR   134144    // 8 warps x 32x64 f32
#define SB_BIAS  199680
#define SB_ESRC  200704
#define SB_CSR   202624
#define SB_CUR   202880
#define SB_INV   203136
#define SB_SEM   203392
#define SB_GEO   203648
#define SB_BYTES 204864

typedef wmma::fragment<wmma::matrix_a, 16, 16, 16, __nv_bfloat16, wmma::row_major> FragA;
typedef wmma::fragment<wmma::matrix_b, 16, 16, 16, __nv_bfloat16, wmma::row_major> FragB;
typedef wmma::fragment<wmma::accumulator, 16, 16, 16, float> FragC;

__global__ __launch_bounds__(256, 1)
void gnn_main(const float* __restrict__ geometry, const int* __restrict__ semantic,
              const int* __restrict__ esrc_g, const int* __restrict__ edst_g,
              const float* __restrict__ Wlot,
              const float* __restrict__ b1, const float* __restrict__ b2,
              const float* __restrict__ b3) {
    extern __shared__ char smem[];
    const int bx = blockIdx.x, t = threadIdx.x;
    const int wid = t >> 5, lane = t & 31;

    __nv_bfloat16* hhi = (__nv_bfloat16*)(smem + SB_HHI);
    __nv_bfloat16* hlo = (__nv_bfloat16*)(smem + SB_HLO);
    float* scr_all = (float*)(smem + SB_SCR);
    float* bias_s  = (float*)(smem + SB_BIAS);
    int*   esrc    = (int*)(smem + SB_ESRC);
    int*   csr     = (int*)(smem + SB_CSR);
    int*   cur     = (int*)(smem + SB_CUR);
    float* inv     = (float*)(smem + SB_INV);
    int*   sem     = (int*)(smem + SB_SEM);
    float* geo     = (float*)(smem + SB_GEO);
    const uint32_t bst_u32 = smem_u32(smem + SB_BST);

    // ---- metadata for 2 graphs ----
    if (t < 60) { cur[t] = 0; sem[t] = semantic[bx * 60 + t]; }
    for (int i = t; i < 300; i += 256) geo[i] = geometry[bx * 300 + i];
    __syncthreads();
    int e_ls[2], e_ld[2], e_g[2];
    #pragma unroll
    for (int r = 0; r < 2; r++) {
        const int e = t + r * 256;
        e_ls[r] = -1;
        if (e < 480) {
            const int g = e / 240, gg = bx * 2 + g;
            e_g[r] = g;
            e_ls[r] = esrc_g[gg * EPG + (e - g * 240)] - gg * NB;
            e_ld[r] = edst_g[gg * EPG + (e - g * 240)] - gg * NB;
            atomicAdd(&cur[g * NB + e_ld[r]], 1);
        }
    }
    __syncthreads();
    if (t < 2) {
        int off = 0;
        for (int v = 0; v < NB; v++) { csr[t * 31 + v] = off; off += cur[t * NB + v]; }
        csr[t * 31 + NB] = off;
    }
    __syncthreads();
    if (t < 64) {
        const int g = t >> 5, v = t & 31;
        float iv = 0.f;
        if (v < NB) {
            const int c = csr[g * 31 + v + 1] - csr[g * 31 + v];
            iv = (c > 0) ? (1.0f / c) : 0.f;
        }
        inv[t] = iv;
    }
    if (t < 60) cur[t] = csr[(t / NB) * 31 + (t % NB)];
    __syncthreads();
    #pragma unroll
    for (int r = 0; r < 2; r++) {
        if (e_ls[r] >= 0) {
            const int g = e_g[r];
            const int pos = atomicAdd(&cur[g * NB + e_ld[r]], 1);
            esrc[g * 240 + pos] = e_ls[r];
        }
    }

    // ---- phase 1 ----
    {
        const int col = t;
        const float ba = d_biasA[col];
        const __nv_bfloat16 z = __float2bfloat16(0.f);
        #pragma unroll
        for (int g = 0; g < 2; g++) {
            float m = 0.f;
            for (int v = 0; v < NB; v++) {
                float acc = ba + d_tab2[sem[g * NB + v] * D + col] + Wlot[(2 * D + v) * D + col];
                #pragma unroll
                for (int j = 0; j < 5; j++)
                    acc = fmaf(geo[(g * NB + v) * 5 + j], d_Wg2[j * D + col], acc);
                acc = fmaxf(acc, 0.f);
                m = fmaxf(m, acc);
                const __nv_bfloat16 hi = __float2bfloat16(acc);
                hhi[(32 * g + v) * LDH + col] = hi;
                hlo[(32 * g + v) * LDH + col] = __float2bfloat16(acc - __bfloat162float(hi));
            }
            hhi[(32 * g + 30) * LDH + col] = z;  hlo[(32 * g + 30) * LDH + col] = z;
            hhi[(32 * g + 31) * LDH + col] = z;  hlo[(32 * g + 31) * LDH + col] = z;
            d_gcat[(bx * 2 + g) * 1024 + col] = m;
        }
    }

    // ---- layers ----
    const float* biases[3] = {b1, b2, b3};
    const int nw = wid;
    float* scr = scr_all + wid * 2048;

    for (int L = 0; L < 3; L++) {
        bias_s[t] = biases[L][t];
        __syncthreads();

        // prefetch chunk 0 into buf 0
        {
            #pragma unroll
            for (int i = 0; i < 8; i++) {
                const int op = t + i * 256;
                const int p = op >> 10, rem = op & 1023, kl = rem >> 6, seg = rem & 63;
                cpa16(bst_u32 + (uint32_t)((0 * 2 + p) * 16640 + kl * 1040 + seg * 16),
                      d_Wb + (((size_t)(L * 2 + p) * 256 + kl) * 512 + seg * 8));
            }
            CPA_COMMIT();
        }

        FragC acc[2][2][4];
        #pragma unroll
        for (int mh = 0; mh < 2; mh++)
            #pragma unroll
            for (int mi = 0; mi < 2; mi++)
                #pragma unroll
                for (int ni = 0; ni < 4; ni++)
                    wmma::fill_fragment(acc[mh][mi][ni], 0.f);

        for (int ks = 0; ks < 16; ks++) {
            const int buf = ks & 1;
            if (ks < 15) {
                const int nb_ = (ks + 1) & 1;
                #pragma unroll
                for (int i = 0; i < 8; i++) {
                    const int op = t + i * 256;
                    const int p = op >> 10, rem = op & 1023, kl = rem >> 6, seg = rem & 63;
                    cpa16(bst_u32 + (uint32_t)((nb_ * 2 + p) * 16640 + kl * 1040 + seg * 16),
                          d_Wb + (((size_t)(L * 2 + p) * 256 + (ks + 1) * 16 + kl) * 512 + seg * 8));
                }
                CPA_COMMIT();
                CPA_WAIT(1);
            } else {
                CPA_WAIT(0);
            }
            __syncthreads();

            const __nv_bfloat16* bs_hi = (const __nv_bfloat16*)(smem + SB_BST + (buf * 2 + 0) * 16640);
            const __nv_bfloat16* bs_lo = (const __nv_bfloat16*)(smem + SB_BST + (buf * 2 + 1) * 16640);
            const int k0 = ks * 16;

            FragB Bhi[4], Blo[4];
            #pragma unroll
            for (int ni = 0; ni < 4; ni++) {
                wmma::load_matrix_sync(Bhi[ni], bs_hi + nw * 64 + ni * 16, 520);
                wmma::load_matrix_sync(Blo[ni], bs_lo + nw * 64 + ni * 16, 520);
            }
            #pragma unroll
            for (int mh = 0; mh < 2; mh++) {
                FragA Ahi[2], Alo[2];
                #pragma unroll
                for (int mi = 0; mi < 2; mi++) {
                    wmma::load_matrix_sync(Ahi[mi], hhi + (mh * 32 + mi * 16) * LDH + k0, LDH);
                    wmma::load_matrix_sync(Alo[mi], hlo + (mh * 32 + mi * 16) * LDH + k0, LDH);
                }
                #pragma unroll
                for (int mi = 0; mi < 2; mi++)
                    #pragma unroll
                    for (int ni = 0; ni < 4; ni++) {
                        wmma::mma_sync(acc[mh][mi][ni], Ahi[mi], Bhi[ni], acc[mh][mi][ni]);
                        wmma::mma_sync(acc[mh][mi][ni], Alo[mi], Bhi[ni], acc[mh][mi][ni]);
                        wmma::mma_sync(acc[mh][mi][ni], Ahi[mi], Blo[ni], acc[mh][mi][ni]);
                    }
            }
            __syncthreads();
        }

        // ---- epilogue ----
        const float bias = bias_s[nw * 32 + lane];
        #pragma unroll
        for (int mh = 0; mh < 2; mh++) {
            #pragma unroll
            for (int mi = 0; mi < 2; mi++)
                #pragma unroll
                for (int ni = 0; ni < 4; ni++)
                    wmma::store_matrix_sync(scr + mi * 16 * 64 + ni * 16, acc[mh][mi][ni],
                                            64, wmma::mem_row_major);
            __syncwarp();
            const int g = mh;
            float gm = 0.f;
            for (int v = 0; v < NB; v++) {
                float a = 0.f;
                const int e0 = csr[g * 31 + v], e1 = csr[g * 31 + v + 1];
                for (int e = e0; e < e1; e++)
                    a += scr[esrc[g * 240 + e] * 64 + 32 + lane];
                const float iv = inv[g * 32 + v];
                float val = scr[v * 64 + lane] + iv * a + bias;
                val = fmaxf(val, 0.f);
                val = (iv > 0.f) ? val : 0.f;
                gm = fmaxf(gm, val);
                const __nv_bfloat16 hi = __float2bfloat16(val);
                hhi[(32 * g + v) * LDH + nw * 32 + lane] = hi;
                hlo[(32 * g + v) * LDH + nw * 32 + lane] =
                    __float2bfloat16(val - __bfloat162float(hi));
            }
            d_gcat[(bx * 2 + g) * 1024 + (L + 1) * 256 + nw * 32 + lane] = gm;
            __syncwarp();
        }
        __syncthreads();
    }
}

// ---------------- head: WMMA bf16x3, 32 graphs/CTA ----------------
#define HB_LATH 0          // 32x264 bf16
#define HB_LATL 16896
#define HB_BU   33792      // union: B1 dbuf / f32 scr / B2 dbuf / out scr (66560)
#define HB_A    100352     // Ahi 32x24 + Alo 32x24 bf16 = 3072
#define HB_BAGG 103424     // 256 f
#define HB_BMV  104448     // 512 f
#define HB_BYTES 106496

__global__ __launch_bounds__(256, 2)
void head_kernel(const float* __restrict__ bagg, const float* __restrict__ bmu,
                 const float* __restrict__ bvar, float* __restrict__ out) {
    extern __shared__ char smem[];
    const int bx = blockIdx.x, t = threadIdx.x;
    const int wid = t >> 5;
    const int g0 = bx * 32;

    __nv_bfloat16* lath = (__nv_bfloat16*)(smem + HB_LATH);
    __nv_bfloat16* latl = (__nv_bfloat16*)(smem + HB_LATL);
    __nv_bfloat16* Ahi  = (__nv_bfloat16*)(smem + HB_A);
    __nv_bfloat16* Alo  = (__nv_bfloat16*)(smem + HB_A + 1536);
    float* bagg_s = (float*)(smem + HB_BAGG);
    float* bmv_s  = (float*)(smem + HB_BMV);
    const uint32_t bu_u32 = smem_u32(smem + HB_BU);

    if (t < 256) bagg_s[t] = bagg[t];
    bmv_s[t] = bmu[t];
    bmv_s[256 + t] = bvar[t];

    // ---- GEMM1: latent[32][256] = gcat[32][1024] @ Wagg ----
    const int arow = t >> 3, acol = (t & 7) * 2;
    float2 curA = *(const float2*)(d_gcat + (size_t)(g0 + arow) * 1024 + acol);

    // prefetch B chunk 0
    #pragma unroll
    for (int i = 0; i < 4; i++) {
        const int op = t + i * 256;                      // 1024 ops
        const int p = op >> 9, rem = op & 511, kl = rem >> 5, seg = rem & 31;
        cpa16(bu_u32 + (uint32_t)((0 * 2 + p) * 8448 + kl * 528 + seg * 16),
              d_Wagg_b + (((size_t)p * 1024 + kl) * 256 + seg * 8));
    }
    CPA_COMMIT();

    FragC acc1[2][2];
    #pragma unroll
    for (int mi = 0; mi < 2; mi++)
        #pragma unroll
        for (int ni = 0; ni < 2; ni++)
            wmma::fill_fragment(acc1[mi][ni], 0.f);

    for (int ks = 0; ks < 64; ks++) {
        const int buf = ks & 1;
        float2 nxtA;
        if (ks < 63) {
            nxtA = *(const float2*)(d_gcat + (size_t)(g0 + arow) * 1024 + (ks + 1) * 16 + acol);
            const int nb_ = (ks + 1) & 1;
            #pragma unroll
            for (int i = 0; i < 4; i++) {
                const int op = t + i * 256;
                const int p = op >> 9, rem = op & 511, kl = rem >> 5, seg = rem & 31;
                cpa16(bu_u32 + (uint32_t)((nb_ * 2 + p) * 8448 + kl * 528 + seg * 16),
                      d_Wagg_b + (((size_t)p * 1024 + (ks + 1) * 16 + kl) * 256 + seg * 8));
            }
            CPA_COMMIT();
            CPA_WAIT(1);
        } else {
            CPA_WAIT(0);
        }
        // write A chunk (prev reads protected by trailing sync)
        {
            const __nv_bfloat16 h0 = __float2bfloat16(curA.x);
            const __nv_bfloat16 h1 = __float2bfloat16(curA.y);
            Ahi[arow * 24 + acol]     = h0;
            Ahi[arow * 24 + acol + 1] = h1;
            Alo[arow * 24 + acol]     = __float2bfloat16(curA.x - __bfloat162float(h0));
            Alo[arow * 24 + acol + 1] = __float2bfloat16(curA.y - __bfloat162float(h1));
        }
        __syncthreads();

        const __nv_bfloat16* bs_hi = (const __nv_bfloat16*)(smem + HB_BU + (buf * 2 + 0) * 8448);
        const __nv_bfloat16* bs_lo = (const __nv_bfloat16*)(smem + HB_BU + (buf * 2 + 1) * 8448);
        FragA fAh[2], fAl[2];
        FragB fBh[2], fBl[2];
        #pragma unroll
        for (int mi = 0; mi < 2; mi++) {
            wmma::load_matrix_sync(fAh[mi], Ahi + mi * 16 * 24, 24);
            wmma::load_matrix_sync(fAl[mi], Alo + mi * 16 * 24, 24);
        }
        #pragma unroll
        for (int ni = 0; ni < 2; ni++) {
            wmma::load_matrix_sync(fBh[ni], bs_hi + wid * 32 + ni * 16, 264);
            wmma::load_matrix_sync(fBl[ni], bs_lo + wid * 32 + ni * 16, 264);
        }
        #pragma unroll
        for (int mi = 0; mi < 2; mi++)
            #pragma unroll
            for (int ni = 0; ni < 2; ni++) {
                wmma::mma_sync(acc1[mi][ni], fAh[mi], fBh[ni], acc1[mi][ni]);
                wmma::mma_sync(acc1[mi][ni], fAl[mi], fBh[ni], acc1[mi][ni]);
                wmma::mma_sync(acc1[mi][ni], fAh[mi], fBl[ni], acc1[mi][ni]);
            }
        __syncthreads();
        curA = nxtA;
    }

    // latent: store acc1 -> f32 scratch -> +bias -> hi/lo smem
    {
        float* scrf = (float*)(smem + HB_BU);            // 32x256 f32
        #pragma unroll
        for (int mi = 0; mi < 2; mi++)
            #pragma unroll
            for (int ni = 0; ni < 2; ni++)
                wmma::store_matrix_sync(scrf + mi * 16 * 256 + wid * 32 + ni * 16,
                                        acc1[mi][ni], 256, wmma::mem_row_major);
        __syncthreads();
        #pragma unroll
        for (int j = 0; j < 32; j++) {
            const int idx = t + j * 256;                 // 8192
            const int row = idx >> 8, n = idx & 255;
            const float lat = scrf[row * 256 + n] + bagg_s[n];
            const __nv_bfloat16 hi = __float2bfloat16(lat);
            lath[row * 264 + n] = hi;
            latl[row * 264 + n] = __float2bfloat16(lat - __bfloat162float(hi));
        }
        __syncthreads();
    }

    // ---- GEMM2: [32][512] = latent[32][256] @ (Wmu|Wvar) ----
    #pragma unroll
    for (int i = 0; i < 8; i++) {                        // prefetch chunk 0: 2048 ops
        const int op = t + i * 256;
        const int p = op >> 10, rem = op & 1023, kl = rem >> 6, seg = rem & 63;
        cpa16(bu_u32 + (uint32_t)((0 * 2 + p) * 16640 + kl * 1040 + seg * 16),
              d_Wmv_b + (((size_t)p * 256 + kl) * 512 + seg * 8));
    }
    CPA_COMMIT();

    FragC acc2[2][4];
    #pragma unroll
    for (int mi = 0; mi < 2; mi++)
        #pragma unroll
        for (int ni = 0; ni < 4; ni++)
            wmma::fill_fragment(acc2[mi][ni], 0.f);

    for (int ks = 0; ks < 16; ks++) {
        const int buf = ks & 1;
        if (ks < 15) {
            const int nb_ = (ks + 1) & 1;
            #pragma unroll
            for (int i = 0; i < 8; i++) {
                const int op = t + i * 256;
                const int p = op >> 10, rem = op & 1023, kl = rem >> 6, seg = rem & 63;
                cpa16(bu_u32 + (uint32_t)((nb_ * 2 + p) * 16640 + kl * 1040 + seg * 16),
                      d_Wmv_b + (((size_t)p * 256 + (ks + 1) * 16 + kl) * 512 + seg * 8));
            }
            CPA_COMMIT();
            CPA_WAIT(1);
        } else {
            CPA_WAIT(0);
        }
        __syncthreads();
        const __nv_bfloat16* bs_hi = (const __nv_bfloat16*)(smem + HB_BU + (buf * 2 + 0) * 16640);
        const __nv_bfloat16* bs_lo = (const __nv_bfloat16*)(smem + HB_BU + (buf * 2 + 1) * 16640);
        const int k0 = ks * 16;
        FragA fAh[2], fAl[2];
        FragB fBh[4], fBl[4];
        #pragma unroll
        for (int mi = 0; mi < 2; mi++) {
            wmma::load_matrix_sync(fAh[mi], lath + mi * 16 * 264 + k0, 264);
            wmma::load_matrix_sync(fAl[mi], latl + mi * 16 * 264 + k0, 264);
        }
        #pragma unroll
        for (int ni = 0; ni < 4; ni++) {
            wmma::load_matrix_sync(fBh[ni], bs_hi + wid * 64 + ni * 16, 520);
            wmma::load_matrix_sync(fBl[ni], bs_lo + wid * 64 + ni * 16, 520);
        }
        #pragma unroll
        for (int mi = 0; mi < 2; mi++)
            #pragma unroll
            for (int ni = 0; ni < 4; ni++) {
                wmma::mma_sync(acc2[mi][ni], fAh[mi], fBh[ni], acc2[mi][ni]);
                wmma::mma_sync(acc2[mi][ni], fAl[mi], fBh[ni], acc2[mi][ni]);
                wmma::mma_sync(acc2[mi][ni], fAh[mi], fBl[ni], acc2[mi][ni]);
            }
        __syncthreads();
    }

    // output: acc2 -> f32 scratch -> +bias -> out
    {
        float* scrf = (float*)(smem + HB_BU);            // 32x512 f32
        #pragma unroll
        for (int mi = 0; mi < 2; mi++)
            #pragma unroll
            for (int ni = 0; ni < 4; ni++)
                wmma::store_matrix_sync(scrf + mi * 16 * 512 + wid * 64 + ni * 16,
                                        acc2[mi][ni], 512, wmma::mem_row_major);
        __syncthreads();
        #pragma unroll
        for (int j = 0; j < 64; j++) {
            const int idx = t + j * 256;                 // 16384
            const int g = idx >> 9, n = idx & 511;
            const float val = scrf[g * 512 + n] + bmv_s[n];
            if (n < 256)
                out[(size_t)(g0 + g) * 256 + n] = val;
            else
                out[(size_t)NGRAPH * 256 + (size_t)(g0 + g) * 256 + (n - 256)] = val;
        }
    }
}

// ---------------- launch ----------------
extern "C" void kernel_launch(void* const* d_in, const int* in_sizes, int n_in,
                              void* d_out, int out_size) {
    (void)in_sizes; (void)n_in; (void)out_size;
    const float* geometry   = (const float*)d_in[0];
    const int*   semantic   = (const int*)  d_in[1];
    const int*   edge_index = (const int*)  d_in[2];
    const float* W_geo = (const float*)d_in[4];
    const float* b_geo = (const float*)d_in[5];
    const float* emb   = (const float*)d_in[6];
    const float* W_lot = (const float*)d_in[7];
    const float* b_lot = (const float*)d_in[8];
    const float* W1    = (const float*)d_in[9];
    const float* b1    = (const float*)d_in[10];
    const float* W2    = (const float*)d_in[11];
    const float* b2    = (const float*)d_in[12];
    const float* W3    = (const float*)d_in[13];
    const float* b3    = (const float*)d_in[14];
    const float* W_agg = (const float*)d_in[15];
    const float* b_agg = (const float*)d_in[16];
    const float* W_mu  = (const float*)d_in[17];
    const float* b_mu  = (const float*)d_in[18];
    const float* W_var = (const float*)d_in[19];
    const float* b_var = (const float*)d_in[20];

    cudaFuncSetAttribute((const void*)gnn_main,
                         cudaFuncAttributeMaxDynamicSharedMemorySize, SB_BYTES);
    cudaFuncSetAttribute((const void*)head_kernel,
                         cudaFuncAttributeMaxDynamicSharedMemorySize, HB_BYTES);

    precompute_kernel<<<17, 256>>>(W_geo, b_geo, emb, W_lot, b_lot);
    wsplit_kernel<<<3 * 512, 256>>>(W1, W2, W3);
    whead_agg<<<1024, 256>>>(W_agg);
    whead_mv<<<256, 512>>>(W_mu, W_var);
    gnn_main<<<NCTA, 256, SB_BYTES>>>(geometry, semantic,
                                      edge_index, edge_index + NE,
                                      W_lot, b1, b2, b3);
    head_kernel<<<NGRAPH / 32, 256, HB_BYTES>>>(b_agg, b_mu, b_var, (float*)d_out);
}